// round 13
// baseline (speedup 1.0000x reference)
#include <cuda_runtime.h>
#include <cuda_bf16.h>
#include <cstdint>

#define BB 8
#define CC 1024
#define HWD 4096
#define KK 64
#define PP (BB*HWD)   // 32768 pixels

// ---------------- scratch (device globals; no allocation allowed) ----------------
__device__ float    g_gnT[CC*KK];
__device__ int      g_idx[PP];
__device__ float    g_cnt[BB*KK];
__device__ int      g_icnt[BB*KK];
__device__ int      g_off[BB*KK];
__device__ int      g_cur[BB*KK];
__device__ uint16_t g_sp[PP];
__device__ uint8_t  g_sk[PP];
__device__ float    g_cl[BB*KK*CC];
__device__ float    g_w[PP];
__device__ __nv_bfloat16 g_xh[(size_t)PP*CC];   // x_cal hi, pixel-major [b*HWD+p][c]
__device__ __nv_bfloat16 g_xl[(size_t)PP*CC];   // x_cal lo
__device__ __nv_bfloat16 g_wh[CC*CC];           // W hi  [o][c]
__device__ __nv_bfloat16 g_wl[CC*CC];           // W lo

// ---------------- packed f32x2 helpers (kassign) ----------------
__device__ __forceinline__ void ffma2(unsigned long long &acc, unsigned long long a, unsigned long long b){
    asm("fma.rn.f32x2 %0, %1, %2, %0;" : "+l"(acc) : "l"(a), "l"(b));
}
__device__ __forceinline__ unsigned long long dup2(float v){
    unsigned long long r; unsigned int u = __float_as_uint(v);
    asm("mov.b64 %0, {%1, %1};" : "=l"(r) : "r"(u));
    return r;
}
__device__ __forceinline__ float2 unpack2(unsigned long long v){
    unsigned int lo, hi;
    asm("mov.b64 {%0, %1}, %2;" : "=r"(lo), "=r"(hi) : "l"(v));
    return make_float2(__uint_as_float(lo), __uint_as_float(hi));
}

// ---------------- smem / cp.async / mma helpers (baseline PTX, no 'a' features) ----
__device__ __forceinline__ uint32_t smem_u32(const void* p){
    uint32_t a;
    asm("{ .reg .u64 t; cvta.to.shared.u64 t, %1; cvt.u32.u64 %0, t; }" : "=r"(a) : "l"(p));
    return a;
}
#define CP_ASYNC16(sa, ga) asm volatile("cp.async.cg.shared.global [%0], [%1], 16;" :: "r"(sa), "l"(ga))
#define CP_COMMIT()        asm volatile("cp.async.commit_group;" ::: "memory")
#define CP_WAIT0()         asm volatile("cp.async.wait_group 0;" ::: "memory")

__device__ __forceinline__ void ldsm_x4(uint32_t* r, uint32_t addr){
    asm volatile("ldmatrix.sync.aligned.m8n8.x4.shared.b16 {%0,%1,%2,%3}, [%4];"
        : "=r"(r[0]), "=r"(r[1]), "=r"(r[2]), "=r"(r[3]) : "r"(addr));
}
__device__ __forceinline__ void mma_bf16(float* d, const uint32_t* a, const uint32_t* b){
    asm volatile("mma.sync.aligned.m16n8k16.row.col.f32.bf16.bf16.f32 "
        "{%0,%1,%2,%3}, {%4,%5,%6,%7}, {%8,%9}, {%0,%1,%2,%3};"
        : "+f"(d[0]), "+f"(d[1]), "+f"(d[2]), "+f"(d[3])
        : "r"(a[0]), "r"(a[1]), "r"(a[2]), "r"(a[3]), "r"(b[0]), "r"(b[1]));
}
#define SW128(o) ((o) ^ (((o) >> 3) & 0x70))

// ---------------- K1: normalize centroids, transposed [c][k] ----------------
__global__ void knorm(const float* __restrict__ cen){
    int k = blockIdx.x;
    __shared__ float red[256];
    float s = 0.f;
    for(int c = threadIdx.x; c < CC; c += 256){ float v = cen[k*CC+c]; s += v*v; }
    red[threadIdx.x] = s; __syncthreads();
    for(int o = 128; o > 0; o >>= 1){
        if(threadIdx.x < o) red[threadIdx.x] += red[threadIdx.x + o];
        __syncthreads();
    }
    float inv = 1.0f / fmaxf(sqrtf(red[0]), 1e-12f);
    for(int c = threadIdx.x; c < CC; c += 256) g_gnT[c*KK + k] = cen[k*CC+c] * inv;
}

// ---------------- K2: nearest-centroid assignment, k-split across 2 halves ------
// 128 pixels/block; threads [0,128) own k 0..31, [128,256) own k 32..63.
// Per-k sums accumulate in the same ascending-c order as before (numerics
// identical per k).  Merge keeps reference first-max tie-breaking: the low-k
// half wins ties.
__global__ __launch_bounds__(256) void kassign(const float* __restrict__ x){
    const int tid  = threadIdx.x;
    const int pi   = tid & 127;
    const int half = tid >> 7;                 // 0: k0..31, 1: k32..63
    const int p    = blockIdx.x*128 + pi;
    const int b    = p >> 12, hw = p & 4095;
    const float* xb = x + (size_t)b*CC*HWD + hw;
    __shared__ ulonglong2 sg[1024];            // 64 ci x 64 k (16 KB)
    __shared__ float sbest[128];
    __shared__ int   sbi[128];

    unsigned long long sims[16];
    #pragma unroll
    for(int i = 0; i < 16; i++) sims[i] = 0ull;

    for(int c0 = 0; c0 < CC; c0 += 64){
        __syncthreads();
        const float4* src = (const float4*)(g_gnT + c0*KK);
        #pragma unroll
        for(int l = 0; l < 4; l++)
            ((float4*)sg)[tid + l*256] = src[tid + l*256];
        __syncthreads();
        #pragma unroll 8
        for(int ci = 0; ci < 64; ci++){
            float xv = xb[(size_t)(c0+ci)*HWD];
            unsigned long long xd = dup2(xv);
            const ulonglong2* row = &sg[ci*16 + half*8];
            #pragma unroll
            for(int j = 0; j < 8; j++){
                ulonglong2 g = row[j];
                ffma2(sims[2*j],   xd, g.x);
                ffma2(sims[2*j+1], xd, g.y);
            }
        }
    }
    float best = -1e30f; int bi = 0;
    #pragma unroll
    for(int i = 0; i < 16; i++){
        float2 v = unpack2(sims[i]);
        if(v.x > best){ best = v.x; bi = 2*i;   }
        if(v.y > best){ best = v.y; bi = 2*i+1; }
    }
    __syncthreads();                 // sg reuse done
    if(half == 1){ sbest[pi] = best; sbi[pi] = bi; }
    __syncthreads();
    if(half == 0){
        float ob = sbest[pi]; int obi = sbi[pi];
        g_idx[p] = (ob > best) ? (obi + 32) : bi;
    }
}

// ---------------- K3: histogram / scan / scatter / zero ----------------
__global__ void khist(){
    __shared__ int cnt[KK];
    if(threadIdx.x < KK) cnt[threadIdx.x] = 0;
    __syncthreads();
    int b = blockIdx.x;
    for(int p = threadIdx.x; p < HWD; p += 256) atomicAdd(&cnt[g_idx[b*HWD + p]], 1);
    __syncthreads();
    if(threadIdx.x < KK){
        g_cnt [b*KK + threadIdx.x] = (float)cnt[threadIdx.x];
        g_icnt[b*KK + threadIdx.x] = cnt[threadIdx.x];
    }
}
__global__ void kscan(){
    int b = blockIdx.x, t = threadIdx.x;
    __shared__ int s[KK];
    s[t] = g_icnt[b*KK + t];
    __syncthreads();
    if(t == 0){ int acc = 0; for(int k = 0; k < KK; k++){ int c = s[k]; s[k] = acc; acc += c; } }
    __syncthreads();
    g_off[b*KK + t] = s[t];
    g_cur[b*KK + t] = s[t];
}
__global__ void kscatter(){
    int p  = blockIdx.x*256 + threadIdx.x;
    int b  = p >> 12, hw = p & 4095;
    int k  = g_idx[p];
    int pos = atomicAdd(&g_cur[b*KK + k], 1);
    g_sp[b*HWD + pos] = (uint16_t)hw;
    g_sk[b*HWD + pos] = (uint8_t)k;
}
__global__ void kzero(){
    int i = blockIdx.x*256 + threadIdx.x;
    ((float4*)g_cl)[i] = make_float4(0.f,0.f,0.f,0.f);
}

// ---------------- K4: cluster sums via sorted runs ----------------
__global__ __launch_bounds__(256) void ksum(const float* __restrict__ x){
    int b = blockIdx.y, c0 = blockIdx.x*16;
    __shared__ float srow[HWD];
    const int tid = threadIdx.x;
    union { uint4 v;    uint8_t  u[16]; } skv;
    union { uint4 v[2]; uint16_t u[16]; } spv;
    skv.v    = ((const uint4*)(g_sk + b*HWD))[tid];
    spv.v[0] = ((const uint4*)(g_sp + b*HWD))[2*tid];
    spv.v[1] = ((const uint4*)(g_sp + b*HWD))[2*tid + 1];
    for(int ci = 0; ci < 16; ci++){
        int c = c0 + ci;
        __syncthreads();
        const float4* row = (const float4*)(x + ((size_t)b*CC + c)*HWD);
        #pragma unroll
        for(int l = 0; l < 4; l++)
            ((float4*)srow)[tid + l*256] = row[tid + l*256];
        __syncthreads();
        int curk = skv.u[0];
        float s = 0.f;
        #pragma unroll
        for(int j = 0; j < 16; j++){
            int   k2 = skv.u[j];
            float v  = srow[spv.u[j]];
            if(k2 != curk){
                atomicAdd(&g_cl[((size_t)b*KK + curk)*CC + c], s);
                s = 0.f; curk = k2;
            }
            s += v;
        }
        atomicAdd(&g_cl[((size_t)b*KK + curk)*CC + c], s);
    }
}

// ---------------- K5: divide ----------------
__global__ void kdiv(){
    int bk = blockIdx.x;
    float inv = 1.0f / fmaxf(g_cnt[bk], 1.0f);
    for(int c = threadIdx.x; c < CC; c += 256)
        g_cl[(size_t)bk*CC + c] *= inv;
}

// ---------------- K6: calibration weight ----------------
__global__ __launch_bounds__(256) void kw(const float* __restrict__ x){
    int b = blockIdx.y;
    int p = blockIdx.x*256 + threadIdx.x;
    int k = g_idx[b*HWD + p];
    __shared__ float scl[KK][65];
    const float* xb = x + (size_t)b*CC*HWD + p;
    float ssd = 0.f;
    for(int c0 = 0; c0 < CC; c0 += 64){
        __syncthreads();
        for(int i = threadIdx.x; i < KK*64; i += 256){
            int kk = i >> 6, ci = i & 63;
            scl[kk][ci] = g_cl[((size_t)b*KK + kk)*CC + c0 + ci];
        }
        __syncthreads();
        #pragma unroll 8
        for(int ci = 0; ci < 64; ci++){
            float d = scl[k][ci] - xb[(size_t)(c0+ci)*HWD];
            ssd += d*d;
        }
    }
    g_w[b*HWD + p] = expf(-ssd * (1.0f/1024.0f));
}

// ---------------- K6b: split W into bf16 hi/lo ----------------
__global__ void kwsplit(const float* __restrict__ Wt){
    int o = blockIdx.x;
    for(int c = threadIdx.x; c < CC; c += 256){
        float v = Wt[o*CC + c];
        __nv_bfloat16 h = __float2bfloat16_rn(v);
        g_wh[o*CC + c] = h;
        g_wl[o*CC + c] = __float2bfloat16_rn(v - __bfloat162float(h));
    }
}

// ---------------- K7: x_cal, transpose to [p][c], split bf16 hi/lo ----------------
__global__ __launch_bounds__(256) void kconv(const float* __restrict__ x){
    int b  = blockIdx.z;
    int p0 = blockIdx.x*64;
    int c0 = blockIdx.y*64;
    __shared__ float tile[64][65];
    __shared__ float s_w[64];
    __shared__ int   s_k[64];
    int tid = threadIdx.x;
    if(tid < 64){
        s_w[tid] = g_w [b*HWD + p0 + tid];
        s_k[tid] = g_idx[b*HWD + p0 + tid];
    }
    __syncthreads();
    int pi = tid & 63, cq = tid >> 6;
    #pragma unroll
    for(int l = 0; l < 16; l++){
        int ci = l*4 + cq, c = c0 + ci;
        float xv = x[((size_t)b*CC + c)*HWD + p0 + pi];
        int   k  = s_k[pi];
        float cl = g_cl[((size_t)b*KK + k)*CC + c];
        tile[pi][ci] = xv + s_w[pi]*(cl - xv);
    }
    __syncthreads();
    int ci2 = tid & 63, pq = tid >> 6;
    #pragma unroll
    for(int l = 0; l < 16; l++){
        int pi2 = l*4 + pq;
        float v = tile[pi2][ci2];
        __nv_bfloat16 h = __float2bfloat16_rn(v);
        size_t idx = ((size_t)(b*HWD + p0 + pi2))*CC + c0 + ci2;
        g_xh[idx] = h;
        g_xl[idx] = __float2bfloat16_rn(v - __bfloat162float(h));
    }
}

// ---------------- K8: bf16 3-term split GEMM via ldmatrix + mma.sync ----------------
// CTA tile: 128 pixels x 256 out-ch, 512 threads (16 warps, 4M x 4N of 32x64).
// X re-read factor = CC/256 = 4 (was 16) -> DRAM traffic ~537MB; W stays L2-hot.
// Stage 96KB (Xh16|Xl16|Wh32|Wl32), 2 stages = 192KB.  Single sync per K-chunk.
#define XT_SZ    16384
#define WT_SZ    32768
#define STAGE_SZ (2*XT_SZ + 2*WT_SZ)      // 98304
#define GEMM_SMEM (2*STAGE_SZ)            // 196608

__global__ __launch_bounds__(512, 1) void kgemm_mma(const float* __restrict__ bias,
                                                    float* __restrict__ out){
    extern __shared__ char smem[];
    const uint32_t sbase = smem_u32(smem);
    const int tid  = threadIdx.x;
    const int wid  = tid >> 5, lane = tid & 31;
    const int wm   = wid & 3,  wn   = wid >> 2;     // 4 x 4 warp grid
    const int o_base = blockIdx.x*256;
    const int p0     = blockIdx.y*128;
    const int b      = blockIdx.z;

    const char* xh_b = (const char*)g_xh + ((size_t)(b*HWD + p0))*CC*2;
    const char* xl_b = (const char*)g_xl + ((size_t)(b*HWD + p0))*CC*2;
    const char* wh_b = (const char*)g_wh + (size_t)o_base*CC*2;
    const char* wl_b = (const char*)g_wl + (size_t)o_base*CC*2;

    auto load_stage = [&](int st, int chunk){
        uint32_t s0 = sbase + st*STAGE_SZ;
        size_t cb = (size_t)chunk*128;            // 64 bf16 = 128 B within a row
        #pragma unroll
        for(int l = 0; l < 2; l++){               // X tiles: 128 rows x 8 segs
            int j = tid + l*512;
            int r = j >> 3, s = (j & 7)*16;
            uint32_t so = SW128((uint32_t)(r*128 + s));
            size_t go = (size_t)r*(CC*2) + cb + s;
            CP_ASYNC16(s0 + so,         xh_b + go);
            CP_ASYNC16(s0 + XT_SZ + so, xl_b + go);
        }
        #pragma unroll
        for(int l = 0; l < 4; l++){               // W tiles: 256 rows x 8 segs
            int j = tid + l*512;
            int r = j >> 3, s = (j & 7)*16;
            uint32_t so = SW128((uint32_t)(r*128 + s));
            size_t go = (size_t)r*(CC*2) + cb + s;
            CP_ASYNC16(s0 + 2*XT_SZ + so,         wh_b + go);
            CP_ASYNC16(s0 + 2*XT_SZ + WT_SZ + so, wl_b + go);
        }
    };

    float acc[2][8][4];
    #pragma unroll
    for(int m = 0; m < 2; m++)
        #pragma unroll
        for(int n = 0; n < 8; n++)
            #pragma unroll
            for(int q = 0; q < 4; q++) acc[m][n][q] = 0.f;

    // ldmatrix per-lane offsets (within a tile, before swizzle)
    const int arow = wm*32 + (lane & 15);                       // + mt*16
    const int acol = (lane >> 4)*16;                            // k-half byte offset
    const int brow = wn*64 + (lane & 7) + ((lane >> 4) & 1)*8;  // + nt*16
    const int bcol = ((lane >> 3) & 1)*16;

    load_stage(0, 0);
    CP_COMMIT();

    for(int i = 0; i < 16; i++){
        const int st = i & 1;
        CP_WAIT0();              // chunk i resident
        __syncthreads();         // all warps done with buffer st^1 (chunk i-1)
        if(i + 1 < 16){
            load_stage(st ^ 1, i + 1);
            CP_COMMIT();
        }

        const uint32_t xh0 = sbase + st*STAGE_SZ;
        const uint32_t xl0 = xh0 + XT_SZ;
        const uint32_t wh0 = xh0 + 2*XT_SZ;
        const uint32_t wl0 = wh0 + WT_SZ;

        #pragma unroll
        for(int ks = 0; ks < 4; ks++){
            const int kb = ks*32;    // k16 byte offset within 128B row
            uint32_t ah[2][4], al[2][4];
            #pragma unroll
            for(int mt = 0; mt < 2; mt++){
                uint32_t off = SW128((uint32_t)((arow + mt*16)*128 + kb + acol));
                ldsm_x4(ah[mt], xh0 + off);
                ldsm_x4(al[mt], xl0 + off);
            }
            #pragma unroll
            for(int nt = 0; nt < 4; nt++){
                uint32_t bh[4], bl[4];
                uint32_t off = SW128((uint32_t)((brow + nt*16)*128 + kb + bcol));
                ldsm_x4(bh, wh0 + off);
                ldsm_x4(bl, wl0 + off);
                #pragma unroll
                for(int mt = 0; mt < 2; mt++){
                    mma_bf16(acc[mt][2*nt],   ah[mt], &bh[0]);
                    mma_bf16(acc[mt][2*nt+1], ah[mt], &bh[2]);
                    mma_bf16(acc[mt][2*nt],   ah[mt], &bl[0]);
                    mma_bf16(acc[mt][2*nt+1], ah[mt], &bl[2]);
                    mma_bf16(acc[mt][2*nt],   al[mt], &bh[0]);
                    mma_bf16(acc[mt][2*nt+1], al[mt], &bh[2]);
                }
            }
        }
    }

    // epilogue: bias + relu, out[b][o][p]
    const int g = lane >> 2, t4 = lane & 3;
    float* ob = out + (size_t)b*CC*HWD;
    #pragma unroll
    for(int n = 0; n < 8; n++){
        int o = o_base + wn*64 + n*8 + t4*2;
        float b0 = bias[o], b1 = bias[o+1];
        float* c0p = ob + (size_t)o*HWD;
        float* c1p = ob + (size_t)(o+1)*HWD;
        #pragma unroll
        for(int m = 0; m < 2; m++){
            int p = p0 + wm*32 + m*16 + g;
            c0p[p]     = fmaxf(acc[m][n][0] + b0, 0.f);
            c1p[p]     = fmaxf(acc[m][n][1] + b1, 0.f);
            c0p[p + 8] = fmaxf(acc[m][n][2] + b0, 0.f);
            c1p[p + 8] = fmaxf(acc[m][n][3] + b1, 0.f);
        }
    }
}

// ---------------- launch ----------------
extern "C" void kernel_launch(void* const* d_in, const int* in_sizes, int n_in,
                              void* d_out, int out_size){
    const float* x   = (const float*)d_in[0];
    const float* cen = (const float*)d_in[1];
    const float* fw  = (const float*)d_in[2];
    const float* fb  = (const float*)d_in[3];
    float* out = (float*)d_out;

    cudaFuncSetAttribute(kgemm_mma, cudaFuncAttributeMaxDynamicSharedMemorySize, GEMM_SMEM);

    knorm    <<<KK, 256>>>(cen);
    kwsplit  <<<CC, 256>>>(fw);
    kzero    <<<(BB*KK*CC/4)/256, 256>>>();
    kassign  <<<PP/128, 256>>>(x);
    khist    <<<BB, 256>>>();
    kscan    <<<BB, KK>>>();
    kscatter <<<PP/256, 256>>>();
    ksum     <<<dim3(64, BB), 256>>>(x);
    kdiv     <<<BB*KK, 256>>>();
    kw       <<<dim3(HWD/256, BB), 256>>>(x);
    kconv    <<<dim3(HWD/64, CC/64, BB), 256>>>(x);
    kgemm_mma<<<dim3(CC/256, HWD/128, BB), 512, GEMM_SMEM>>>(fb, out);
}